// round 1
// baseline (speedup 1.0000x reference)
#include <cuda_runtime.h>
#include <math.h>

// Problem constants
#define XS 540
#define YS 540
#define BATCH 4
#define NBOX 64
#define TILE 16
#define TXN 34          // ceil(540/16)
#define TYN 34
#define NTILES (TXN*TYN)

// scratch: per (batch, tile): [valid_cnt, bce_sum, focal_sum]
__device__ float g_part[BATCH * NTILES * 3];

struct BoxC { float cx, cy, c, s, hw, hl, hv; };

__global__ void __launch_bounds__(256)
hm_loss_tile_kernel(const float* __restrict__ logits,
                    const float* __restrict__ boxes,
                    const float* __restrict__ hm)
{
    __shared__ float braw[NBOX * 7];
    __shared__ BoxC  bc[NBOX];
    __shared__ int   flag[NBOX];
    __shared__ int   list[NBOX];
    __shared__ int   nlist;
    __shared__ float r0[256], r1[256], r2[256];

    const int b   = blockIdx.z;
    const int tid = threadIdx.y * TILE + threadIdx.x;

    // load raw boxes for this batch
    for (int i = tid; i < NBOX * 7; i += 256)
        braw[i] = boxes[b * NBOX * 7 + i];
    __syncthreads();

    // derive per-box constants + cull against this tile's AABB
    if (tid < NBOX) {
        const float* p = &braw[tid * 7];
        BoxC v;
        v.cx = (p[0] + 54.0f) * 5.0f;     // (x - (-54)) / 0.2
        v.cy = (p[1] + 54.0f) * 5.0f;
        v.hw = p[3] * 2.5f;               // (w/0.2)/2
        v.hl = p[4] * 2.5f;
        v.c  =  cosf(p[6]);               // cos(-theta)
        v.s  = -sinf(p[6]);               // sin(-theta)
        v.hv = p[5] * 0.2f;               // h / (3+2)
        bc[tid] = v;

        float ex = fabsf(v.c) * v.hw + fabsf(v.s) * v.hl;
        float ey = fabsf(v.s) * v.hw + fabsf(v.c) * v.hl;
        float x0 = (float)(blockIdx.x * TILE);
        float y0 = (float)(blockIdx.y * TILE);
        float x1 = x0 + (float)(TILE - 1);
        float y1 = y0 + (float)(TILE - 1);
        bool hit = (v.cx - ex <= x1) && (v.cx + ex >= x0) &&
                   (v.cy - ey <= y1) && (v.cy + ey >= y0);
        flag[tid] = hit ? 1 : 0;
    }
    __syncthreads();

    // order-preserving compaction (64 iters serial — negligible)
    if (tid == 0) {
        int n = 0;
        #pragma unroll
        for (int i = 0; i < NBOX; i++)
            if (flag[i]) list[n++] = i;
        nlist = n;
    }
    __syncthreads();
    const int n = nlist;

    const int x = blockIdx.x * TILE + threadIdx.x;
    const int y = blockIdx.y * TILE + threadIdx.y;

    float sv = 0.0f, sb = 0.0f, sf = 0.0f;
    if (x < XS && y < YS) {
        // rasterize: last box wins -> scan culled list from the back
        float gt = 0.0f;
        const float fx = (float)x, fy = (float)y;
        for (int i = n - 1; i >= 0; --i) {
            BoxC v = bc[list[i]];
            float dx = fx - v.cx;
            float dy = fy - v.cy;
            float lx = dx * v.c - dy * v.s;
            float ly = dx * v.s + dy * v.c;
            if (fabsf(lx) <= v.hw && fabsf(ly) <= v.hl) { gt = v.hv; break; }
        }

        const int idx = (b * YS + y) * XS + x;
        const float xv = logits[idx];
        const float hh = hm[idx];

        const bool pos = (gt > 0.0f);
        const bool valid = pos || (hh > 0.0f);   // pos | (neg & point); gt is 0 or >0
        if (valid) {
            const float weight = pos ? 5.0f : 0.1f;
            const float e = __expf(-fabsf(xv));
            const float bce = fmaxf(xv, 0.0f) - xv * gt + log1pf(e);
            const float p  = 1.0f / (1.0f + __expf(-xv));
            const float pt = p * gt + (1.0f - p) * (1.0f - gt);
            const float aw = 0.25f * gt + 0.75f * (1.0f - gt);
            const float om = 1.0f - pt;
            const float fw = om * om * aw * weight;
            sv = 1.0f;
            sb = weight * bce;
            sf = fw * bce;
        }
    }

    // deterministic block tree reduction
    r0[tid] = sv; r1[tid] = sb; r2[tid] = sf;
    __syncthreads();
    #pragma unroll
    for (int st = 128; st > 0; st >>= 1) {
        if (tid < st) {
            r0[tid] += r0[tid + st];
            r1[tid] += r1[tid + st];
            r2[tid] += r2[tid + st];
        }
        __syncthreads();
    }
    if (tid == 0) {
        const int t = blockIdx.y * TXN + blockIdx.x;
        float* o = &g_part[(b * NTILES + t) * 3];
        o[0] = r0[0]; o[1] = r1[0]; o[2] = r2[0];
    }
}

__global__ void __launch_bounds__(256)
hm_loss_final_kernel(float* __restrict__ out)
{
    __shared__ float r0[256], r1[256], r2[256];
    const int tid = threadIdx.x;

    float total = 0.0f, ns = 0.0f;
    for (int b = 0; b < BATCH; b++) {
        float s0 = 0.0f, s1 = 0.0f, s2 = 0.0f;
        for (int t = tid; t < NTILES; t += 256) {
            const float* p = &g_part[(b * NTILES + t) * 3];
            s0 += p[0]; s1 += p[1]; s2 += p[2];
        }
        r0[tid] = s0; r1[tid] = s1; r2[tid] = s2;
        __syncthreads();
        #pragma unroll
        for (int st = 128; st > 0; st >>= 1) {
            if (tid < st) {
                r0[tid] += r0[tid + st];
                r1[tid] += r1[tid + st];
                r2[tid] += r2[tid + st];
            }
            __syncthreads();
        }
        if (tid == 0) {
            const float cnt = r0[0];
            if (cnt > 0.0f) {
                const float denom = fmaxf(cnt, 1.0f);
                total += 0.5f * (r1[0] + r2[0]) / denom;
                ns += 1.0f;
            }
        }
        __syncthreads();
    }
    if (tid == 0)
        out[0] = (ns > 0.0f) ? (total / fmaxf(ns, 1.0f)) : total;
}

extern "C" void kernel_launch(void* const* d_in, const int* in_sizes, int n_in,
                              void* d_out, int out_size)
{
    // Expected order per reference: attention_logits, boxes, height_maps.
    // Defensive remap: boxes is uniquely sized (4*64*7 = 1792).
    const float* arrs[3] = { (const float*)d_in[0],
                             (const float*)d_in[1],
                             (const float*)d_in[2] };
    const float* boxes = arrs[1];
    const float* logits = arrs[0];
    const float* hmap = arrs[2];
    if (n_in >= 3) {
        int bi = -1;
        for (int i = 0; i < 3; i++)
            if (in_sizes[i] == BATCH * NBOX * 7) { bi = i; break; }
        if (bi >= 0) {
            boxes = arrs[bi];
            int o0 = -1, o1 = -1;
            for (int i = 0; i < 3; i++) {
                if (i == bi) continue;
                if (o0 < 0) o0 = i; else o1 = i;
            }
            logits = arrs[o0];
            hmap   = arrs[o1];
        }
    }

    dim3 block(TILE, TILE, 1);
    dim3 grid(TXN, TYN, BATCH);
    hm_loss_tile_kernel<<<grid, block>>>(logits, boxes, hmap);
    hm_loss_final_kernel<<<1, 256>>>((float*)d_out);
}

// round 2
// speedup vs baseline: 1.7317x; 1.7317x over previous
#include <cuda_runtime.h>
#include <math.h>

#define XS 540
#define YS 540
#define BATCH 4
#define NBOX 64
#define TILE_X 32
#define TILE_Y 32
#define TXN 17          // ceil(540/32)
#define TYN 17
#define NBLOCKS (TXN*TYN*BATCH)
#define FIXSCALE 67108864.0   // 2^26

// Deterministic integer accumulators: [batch][0]=valid cnt, [1]=bce*2^26, [2]=focal*2^26
__device__ unsigned long long g_acc[BATCH][3];
__device__ unsigned int g_done;

struct BoxC { float cx, cy, c, s, hw, hl, hv; };

__global__ void __launch_bounds__(256)
hm_loss_fused_kernel(const float* __restrict__ logits,
                     const float* __restrict__ boxes,
                     const float* __restrict__ hm,
                     float* __restrict__ out)
{
    __shared__ float braw[NBOX * 7];
    __shared__ BoxC  bc[NBOX];
    __shared__ int   flag[NBOX];
    __shared__ int   list[NBOX];
    __shared__ int   nlist;
    __shared__ float w0[8], w1[8], w2[8];

    const int b   = blockIdx.z;
    const int tid = threadIdx.x;

    // load raw boxes for this batch
    for (int i = tid; i < NBOX * 7; i += 256)
        braw[i] = boxes[b * NBOX * 7 + i];
    __syncthreads();

    // per-box constants + cull against this tile's AABB
    if (tid < NBOX) {
        const float* p = &braw[tid * 7];
        BoxC v;
        v.cx = (p[0] + 54.0f) * 5.0f;
        v.cy = (p[1] + 54.0f) * 5.0f;
        v.hw = p[3] * 2.5f;
        v.hl = p[4] * 2.5f;
        v.c  =  cosf(p[6]);      // cos(-theta)
        v.s  = -sinf(p[6]);      // sin(-theta)
        v.hv = p[5] * 0.2f;
        bc[tid] = v;

        float ex = fabsf(v.c) * v.hw + fabsf(v.s) * v.hl;
        float ey = fabsf(v.s) * v.hw + fabsf(v.c) * v.hl;
        float x0 = (float)(blockIdx.x * TILE_X);
        float y0 = (float)(blockIdx.y * TILE_Y);
        float x1 = x0 + (float)(TILE_X - 1);
        float y1 = y0 + (float)(TILE_Y - 1);
        flag[tid] = ((v.cx - ex <= x1) && (v.cx + ex >= x0) &&
                     (v.cy - ey <= y1) && (v.cy + ey >= y0)) ? 1 : 0;
    }
    __syncthreads();

    if (tid == 0) {
        int n = 0;
        #pragma unroll
        for (int i = 0; i < NBOX; i++)
            if (flag[i]) list[n++] = i;
        nlist = n;
    }
    __syncthreads();
    const int n = nlist;

    const int x  = blockIdx.x * TILE_X + (tid & 31);
    const int y0 = blockIdx.y * TILE_Y + (tid >> 5);

    float sv = 0.0f, sb = 0.0f, sf = 0.0f;

    if (x < XS) {
        const float fx = (float)x;
        #pragma unroll
        for (int k = 0; k < 4; k++) {
            const int y = y0 + 8 * k;
            if (y >= YS) continue;

            // rasterize: last box wins -> scan culled list from the back
            float gt = 0.0f;
            const float fy = (float)y;
            for (int i = n - 1; i >= 0; --i) {
                BoxC v = bc[list[i]];
                float dx = fx - v.cx;
                float dy = fy - v.cy;
                float lx = dx * v.c - dy * v.s;
                float ly = dx * v.s + dy * v.c;
                if (fabsf(lx) <= v.hw && fabsf(ly) <= v.hl) { gt = v.hv; break; }
            }

            const int idx = (b * YS + y) * XS + x;
            const float xv = logits[idx];
            const float hh = hm[idx];

            const bool pos = (gt > 0.0f);
            if (pos || (hh > 0.0f)) {
                const float weight = pos ? 5.0f : 0.1f;
                const float e = __expf(-fabsf(xv));
                const float bce = fmaxf(xv, 0.0f) - xv * gt + log1pf(e);
                const float p  = 1.0f / (1.0f + __expf(-xv));
                const float pt = p * gt + (1.0f - p) * (1.0f - gt);
                const float aw = 0.25f * gt + 0.75f * (1.0f - gt);
                const float om = 1.0f - pt;
                sv += 1.0f;
                sb += weight * bce;
                sf += om * om * aw * weight * bce;
            }
        }
    }

    // warp shuffle reduction
    #pragma unroll
    for (int st = 16; st > 0; st >>= 1) {
        sv += __shfl_xor_sync(0xffffffffu, sv, st);
        sb += __shfl_xor_sync(0xffffffffu, sb, st);
        sf += __shfl_xor_sync(0xffffffffu, sf, st);
    }
    const int lane = tid & 31, wid = tid >> 5;
    if (lane == 0) { w0[wid] = sv; w1[wid] = sb; w2[wid] = sf; }
    __syncthreads();

    if (tid == 0) {
        float t0 = 0.0f, t1 = 0.0f, t2 = 0.0f;
        #pragma unroll
        for (int i = 0; i < 8; i++) { t0 += w0[i]; t1 += w1[i]; t2 += w2[i]; }

        // deterministic fixed-point accumulation (integer adds are associative)
        atomicAdd(&g_acc[b][0], (unsigned long long)(t0 + 0.5f));
        atomicAdd(&g_acc[b][1], (unsigned long long)llrint((double)t1 * FIXSCALE));
        atomicAdd(&g_acc[b][2], (unsigned long long)llrint((double)t2 * FIXSCALE));
        __threadfence();

        unsigned int ticket = atomicAdd(&g_done, 1u);
        if (ticket == NBLOCKS - 1) {
            // last block finishes: compute final scalar, then reset state for next replay
            float total = 0.0f, ns = 0.0f;
            #pragma unroll
            for (int bb = 0; bb < BATCH; bb++) {
                double cnt = (double)g_acc[bb][0];
                if (cnt > 0.0) {
                    double s1 = (double)g_acc[bb][1] / FIXSCALE;
                    double s2 = (double)g_acc[bb][2] / FIXSCALE;
                    total += (float)(0.5 * (s1 + s2) / fmax(cnt, 1.0));
                    ns += 1.0f;
                }
            }
            out[0] = (ns > 0.0f) ? (total / fmaxf(ns, 1.0f)) : total;
            // reset for next graph replay
            #pragma unroll
            for (int bb = 0; bb < BATCH; bb++) {
                g_acc[bb][0] = 0ull; g_acc[bb][1] = 0ull; g_acc[bb][2] = 0ull;
            }
            __threadfence();
            g_done = 0u;
        }
    }
}

extern "C" void kernel_launch(void* const* d_in, const int* in_sizes, int n_in,
                              void* d_out, int out_size)
{
    const float* arrs[3] = { (const float*)d_in[0],
                             (const float*)d_in[1],
                             (const float*)d_in[2] };
    // reference order: attention_logits, boxes, height_maps; remap defensively by size
    const float* logits = arrs[0];
    const float* boxes  = arrs[1];
    const float* hmap   = arrs[2];
    if (n_in >= 3) {
        int bi = -1;
        for (int i = 0; i < 3; i++)
            if (in_sizes[i] == BATCH * NBOX * 7) { bi = i; break; }
        if (bi >= 0) {
            boxes = arrs[bi];
            int o0 = -1, o1 = -1;
            for (int i = 0; i < 3; i++) {
                if (i == bi) continue;
                if (o0 < 0) o0 = i; else o1 = i;
            }
            logits = arrs[o0];
            hmap   = arrs[o1];
        }
    }

    dim3 block(256, 1, 1);
    dim3 grid(TXN, TYN, BATCH);
    hm_loss_fused_kernel<<<grid, block>>>(logits, boxes, hmap, (float*)d_out);
}

// round 3
// speedup vs baseline: 2.3038x; 1.3304x over previous
#include <cuda_runtime.h>
#include <math.h>

#define XS 540
#define YS 540
#define BATCH 4
#define NBOX 64
#define TILE_X 32
#define TILE_Y 32
#define TXN 17
#define TYN 17
#define NBLOCKS (TXN*TYN*BATCH)
#define FIXSCALE 67108864.0   // 2^26

__device__ unsigned long long g_acc[BATCH][3];
__device__ unsigned int g_done;

struct BoxC { float cx, cy, c, s, hw, hl, hv; };

__global__ void __launch_bounds__(256)
hm_loss_fused_kernel(const float* __restrict__ logits,
                     const float* __restrict__ boxes,
                     const float* __restrict__ hm,
                     float* __restrict__ out)
{
    __shared__ float braw[NBOX * 7];
    __shared__ BoxC  bc[NBOX];
    __shared__ int   list[NBOX];
    __shared__ int   cnt0_s;
    __shared__ int   nlist;
    __shared__ float w0[8], w1[8], w2[8];

    const int b   = blockIdx.z;
    const int tid = threadIdx.x;
    const int lane = tid & 31;

    for (int i = tid; i < NBOX * 7; i += 256)
        braw[i] = boxes[b * NBOX * 7 + i];
    __syncthreads();

    // per-box constants + cull + ballot compaction (warps 0 and 1 hold boxes)
    bool hit = false;
    unsigned int m = 0;
    if (tid < NBOX) {
        const float* p = &braw[tid * 7];
        BoxC v;
        v.cx = (p[0] + 54.0f) * 5.0f;
        v.cy = (p[1] + 54.0f) * 5.0f;
        v.hw = p[3] * 2.5f;
        v.hl = p[4] * 2.5f;
        float sn, cn;
        __sincosf(p[6], &sn, &cn);
        v.c  = cn;          // cos(-theta)
        v.s  = -sn;         // sin(-theta)
        v.hv = p[5] * 0.2f;
        bc[tid] = v;

        float ex = fabsf(v.c) * v.hw + fabsf(v.s) * v.hl;
        float ey = fabsf(v.s) * v.hw + fabsf(v.c) * v.hl;
        float x0 = (float)(blockIdx.x * TILE_X);
        float y0 = (float)(blockIdx.y * TILE_Y);
        hit = (v.cx - ex <= x0 + (float)(TILE_X - 1)) && (v.cx + ex >= x0) &&
              (v.cy - ey <= y0 + (float)(TILE_Y - 1)) && (v.cy + ey >= y0);
        m = __ballot_sync(0xffffffffu, hit);
        if (tid == 0) cnt0_s = __popc(m);
    }
    __syncthreads();
    if (tid < NBOX) {
        int base = (tid >= 32) ? cnt0_s : 0;
        if (hit) {
            int rank = base + __popc(m & ((1u << lane) - 1u));
            list[rank] = tid;
        }
        if (tid == 32) nlist = cnt0_s + __popc(m);
        else if (tid == 0 && NBOX <= 32) nlist = cnt0_s;
    }
    __syncthreads();
    const int n = nlist;

    const int x  = blockIdx.x * TILE_X + lane;
    const int y0 = blockIdx.y * TILE_Y + (tid >> 5);
    const bool xok = (x < XS);

    // prefetch all 4 (logit, hm) pairs — 8 LDGs in flight behind raster compute
    float xv[4], hh[4];
    bool yok[4];
    #pragma unroll
    for (int k = 0; k < 4; k++) {
        const int y = y0 + 8 * k;
        yok[k] = xok && (y < YS);
        if (yok[k]) {
            const int idx = (b * YS + y) * XS + x;
            xv[k] = logits[idx];
            hh[k] = hm[idx];
        }
    }

    float sv = 0.0f, sb = 0.0f, sf = 0.0f;
    const float fx = (float)x;

    #pragma unroll
    for (int k = 0; k < 4; k++) {
        if (!yok[k]) continue;
        const float fy = (float)(y0 + 8 * k);

        // rasterize: last box wins -> scan culled list from the back
        float gt = 0.0f;
        for (int i = n - 1; i >= 0; --i) {
            BoxC v = bc[list[i]];
            float dx = fx - v.cx;
            float dy = fy - v.cy;
            float lx = dx * v.c - dy * v.s;
            float ly = dx * v.s + dy * v.c;
            if (fabsf(lx) <= v.hw && fabsf(ly) <= v.hl) { gt = v.hv; break; }
        }

        const float xl = xv[k];
        const bool pos = (gt > 0.0f);
        if (pos || (hh[k] > 0.0f)) {
            const float weight = pos ? 5.0f : 0.1f;
            const float e  = __expf(-fabsf(xl));      // EX2
            const float d  = 1.0f + e;
            const float bce = fmaxf(xl, 0.0f) - xl * gt + __logf(d);  // LG2
            const float rd = __fdividef(1.0f, d);     // RCP
            const float p  = (xl >= 0.0f) ? rd : e * rd;   // sigmoid(xl)
            const float u  = fmaf(p, 1.0f - 2.0f * gt, gt); // 1 - p_t
            const float aw = 0.75f - 0.5f * gt;
            sv += 1.0f;
            sb += weight * bce;
            sf += u * u * aw * weight * bce;
        }
    }

    // warp shuffle reduction
    #pragma unroll
    for (int st = 16; st > 0; st >>= 1) {
        sv += __shfl_xor_sync(0xffffffffu, sv, st);
        sb += __shfl_xor_sync(0xffffffffu, sb, st);
        sf += __shfl_xor_sync(0xffffffffu, sf, st);
    }
    const int wid = tid >> 5;
    if (lane == 0) { w0[wid] = sv; w1[wid] = sb; w2[wid] = sf; }
    __syncthreads();

    if (tid == 0) {
        float t0 = 0.0f, t1 = 0.0f, t2 = 0.0f;
        #pragma unroll
        for (int i = 0; i < 8; i++) { t0 += w0[i]; t1 += w1[i]; t2 += w2[i]; }

        atomicAdd(&g_acc[b][0], (unsigned long long)(t0 + 0.5f));
        atomicAdd(&g_acc[b][1], (unsigned long long)llrint((double)t1 * FIXSCALE));
        atomicAdd(&g_acc[b][2], (unsigned long long)llrint((double)t2 * FIXSCALE));
        __threadfence();

        unsigned int ticket = atomicAdd(&g_done, 1u);
        if (ticket == NBLOCKS - 1) {
            float total = 0.0f, ns = 0.0f;
            #pragma unroll
            for (int bb = 0; bb < BATCH; bb++) {
                double cnt = (double)g_acc[bb][0];
                if (cnt > 0.0) {
                    double s1 = (double)g_acc[bb][1] / FIXSCALE;
                    double s2 = (double)g_acc[bb][2] / FIXSCALE;
                    total += (float)(0.5 * (s1 + s2) / fmax(cnt, 1.0));
                    ns += 1.0f;
                }
            }
            out[0] = (ns > 0.0f) ? (total / fmaxf(ns, 1.0f)) : total;
            #pragma unroll
            for (int bb = 0; bb < BATCH; bb++) {
                g_acc[bb][0] = 0ull; g_acc[bb][1] = 0ull; g_acc[bb][2] = 0ull;
            }
            __threadfence();
            g_done = 0u;
        }
    }
}

extern "C" void kernel_launch(void* const* d_in, const int* in_sizes, int n_in,
                              void* d_out, int out_size)
{
    const float* arrs[3] = { (const float*)d_in[0],
                             (const float*)d_in[1],
                             (const float*)d_in[2] };
    const float* logits = arrs[0];
    const float* boxes  = arrs[1];
    const float* hmap   = arrs[2];
    if (n_in >= 3) {
        int bi = -1;
        for (int i = 0; i < 3; i++)
            if (in_sizes[i] == BATCH * NBOX * 7) { bi = i; break; }
        if (bi >= 0) {
            boxes = arrs[bi];
            int o0 = -1, o1 = -1;
            for (int i = 0; i < 3; i++) {
                if (i == bi) continue;
                if (o0 < 0) o0 = i; else o1 = i;
            }
            logits = arrs[o0];
            hmap   = arrs[o1];
        }
    }

    dim3 block(256, 1, 1);
    dim3 grid(TXN, TYN, BATCH);
    hm_loss_fused_kernel<<<grid, block>>>(logits, boxes, hmap, (float*)d_out);
}